// round 6
// baseline (speedup 1.0000x reference)
#include <cuda_runtime.h>
#include <cuda_bf16.h>
#include <cstdint>

#define NB   4096
#define NK   50
#define ND   64
#define NL   3

// ---------------- scratch (device globals; no allocation allowed) -----------
__device__ __nv_bfloat16 g_Uh[NB * ND];
__device__ __nv_bfloat16 g_Ul[NB * ND];
__device__ __nv_bfloat16 g_Vh[NB * ND];
__device__ __nv_bfloat16 g_Vl[NB * ND];

#define SWZ128(o) ((uint32_t)(o) ^ (((uint32_t)(o) >> 3) & 0x70u))

__device__ __forceinline__ uint32_t smem_u32(const void* p) {
    uint32_t a;
    asm("{ .reg .u64 t; cvta.to.shared.u64 t, %1; cvt.u32.u64 %0, t; }"
        : "=r"(a) : "l"(p));
    return a;
}
__device__ __forceinline__ void cpa16(uint32_t dst, const void* src) {
    asm volatile("cp.async.cg.shared.global [%0], [%1], 16;"
                 :: "r"(dst), "l"(src) : "memory");
}
#define CP_COMMIT() asm volatile("cp.async.commit_group;" ::: "memory")
#define CP_WAIT0()  asm volatile("cp.async.wait_group 0;" ::: "memory")

__device__ __forceinline__ void ldm_x4(uint32_t* r, uint32_t addr) {
    asm volatile("ldmatrix.sync.aligned.m8n8.x4.shared.b16 {%0,%1,%2,%3}, [%4];"
                 : "=r"(r[0]), "=r"(r[1]), "=r"(r[2]), "=r"(r[3]) : "r"(addr));
}
__device__ __forceinline__ void ldm_x2(uint32_t* r, uint32_t addr) {
    asm volatile("ldmatrix.sync.aligned.m8n8.x2.shared.b16 {%0,%1}, [%2];"
                 : "=r"(r[0]), "=r"(r[1]) : "r"(addr));
}
__device__ __forceinline__ void mma16816(float* d, const uint32_t* a,
                                         const uint32_t* b) {
    asm volatile(
        "mma.sync.aligned.m16n8k16.row.col.f32.bf16.bf16.f32 "
        "{%0,%1,%2,%3}, {%4,%5,%6,%7}, {%8,%9}, {%0,%1,%2,%3};"
        : "+f"(d[0]), "+f"(d[1]), "+f"(d[2]), "+f"(d[3])
        : "r"(a[0]), "r"(a[1]), "r"(a[2]), "r"(a[3]), "r"(b[0]), "r"(b[1]));
}

// ---------------------------------------------------------------------------
// Kernel A: gather + weighted neighbor sums (w, w^2, w^3) + 3-layer MLP.
// Block: 256 threads = 8 rows x 32 lanes (float2 per lane). Grid 512.
// W staged one layer at a time (pitch 65 -> conflict-free transpose writes).
// ---------------------------------------------------------------------------
__global__ __launch_bounds__(256)
void gather_mlp(const int* __restrict__ user_ids,
                const int* __restrict__ item_ids,
                const int* __restrict__ nbr,
                const float* __restrict__ mask,
                const float* __restrict__ ut,
                const float* __restrict__ itab,
                const float* __restrict__ Ws,
                const float* __restrict__ bsv)
{
    __shared__ float s_W[ND * 65];     // [in][out] transposed, pitch 65
    __shared__ float s_b[NL][ND];
    __shared__ float s_x[8][ND];
    __shared__ float s_m[8][52];
    __shared__ int   s_n[8][52];

    const int tid = threadIdx.x;
    const int r = tid >> 5;            // 0..7 row
    const int q = tid & 31;            // 0..31 lane -> dims {2q, 2q+1}
    const int b0 = blockIdx.x * 8;
    const int b = b0 + r;

    for (int i = tid; i < 8 * NK; i += 256) {
        int rr = i / NK, kk = i - rr * NK;
        int g = (b0 + rr) * NK + kk;
        s_n[rr][kk] = nbr[g];
        s_m[rr][kk] = mask[g];
    }
    for (int i = tid; i < NL * ND; i += 256)
        s_b[i >> 6][i & 63] = bsv[i];
    // stage W layer 0 transposed: s_W[in*65+out] = Ws[0][out][in]
    for (int i = tid; i < ND * ND; i += 256) {
        int o = i >> 6, in_ = i & 63;
        s_W[in_ * 65 + o] = Ws[i];
    }
    __syncthreads();

    // item gather -> bf16 hi/lo split
    {
        float2 v = *(const float2*)&itab[(long)item_ids[b] * ND + 2 * q];
        __nv_bfloat16 h0 = __float2bfloat16(v.x), h1 = __float2bfloat16(v.y);
        __nv_bfloat162 hh(h0, h1);
        __nv_bfloat162 ll(__float2bfloat16(v.x - __bfloat162float(h0)),
                          __float2bfloat16(v.y - __bfloat162float(h1)));
        int off = b * ND + 2 * q;
        *(__nv_bfloat162*)&g_Vh[off] = hh;
        *(__nv_bfloat162*)&g_Vl[off] = ll;
    }

    float2 u = *(const float2*)&ut[(long)user_ids[b] * ND + 2 * q];

    // one pass: weighted sums for w, w^2, w^3
    float a1x=0,a1y=0, a2x=0,a2y=0, a3x=0,a3y=0;
#pragma unroll
    for (int kb = 0; kb < NK; kb += 10) {
        float2 vv[10]; float ww[10];
#pragma unroll
        for (int j = 0; j < 10; j++) {
            int n = s_n[r][kb + j];
            ww[j] = s_m[r][kb + j];
            vv[j] = *(const float2*)&ut[(long)n * ND + 2 * q];
        }
#pragma unroll
        for (int j = 0; j < 10; j++) {
            float w = ww[j];
            float tx = w * vv[j].x, ty = w * vv[j].y;
            a1x += tx; a1y += ty;
            tx *= w; ty *= w;
            a2x += tx; a2y += ty;
            tx *= w; ty *= w;
            a3x += tx; a3y += ty;
        }
    }
    const float inv = 1.0f / (float)NK;
    float2 sums[3] = { make_float2(a1x*inv, a1y*inv),
                       make_float2(a2x*inv, a2y*inv),
                       make_float2(a3x*inv, a3y*inv) };

    float2 x = u;
#pragma unroll
    for (int l = 0; l < NL; l++) {
        s_x[r][2*q]     = x.x + sums[l].x;
        s_x[r][2*q + 1] = x.y + sums[l].y;
        __syncthreads();
        float ax = s_b[l][2*q], ay = s_b[l][2*q + 1];
#pragma unroll
        for (int i = 0; i < ND; i++) {
            float xi = s_x[r][i];                 // broadcast
            ax = fmaf(xi, s_W[i * 65 + 2*q],     ax);
            ay = fmaf(xi, s_W[i * 65 + 2*q + 1], ay);
        }
        __syncthreads();
        if (l < NL - 1) {
            const float* Wn = Ws + (l + 1) * ND * ND;
            for (int i = tid; i < ND * ND; i += 256) {
                int o = i >> 6, in_ = i & 63;
                s_W[in_ * 65 + o] = Wn[i];
            }
        }
        x = make_float2(fmaxf(ax, 0.f), fmaxf(ay, 0.f));
    }

    // U bf16 hi/lo split
    {
        __nv_bfloat16 h0 = __float2bfloat16(x.x), h1 = __float2bfloat16(x.y);
        __nv_bfloat162 hh(h0, h1);
        __nv_bfloat162 ll(__float2bfloat16(x.x - __bfloat162float(h0)),
                          __float2bfloat16(x.y - __bfloat162float(h1)));
        int off = b * ND + 2 * q;
        *(__nv_bfloat162*)&g_Uh[off] = hh;
        *(__nv_bfloat162*)&g_Ul[off] = ll;
    }
}

// ---------------------------------------------------------------------------
// Kernel B: C = U @ V^T via mma.sync m16n8k16 bf16, hi/lo split (3 products).
// CTA 128x128, 8 warps (2m x 4n), warp tile 64x32. K=64 smem-resident.
// 64 KB dyn smem; launch_bounds(256,2) -> <=128 regs -> 2 CTAs/SM.
// ---------------------------------------------------------------------------
#define SM_AH 0
#define SM_AL 16384
#define SM_BH 32768
#define SM_BL 49152
#define SM_GEMM 65536

__global__ __launch_bounds__(256, 2)
void score_gemm_mma(float* __restrict__ C)
{
    extern __shared__ char smem[];
    const uint32_t sb = smem_u32(smem);
    const int tid = threadIdx.x;
    const int wid = tid >> 5, lid = tid & 31;
    const int bM = blockIdx.y * 128;
    const int bN = blockIdx.x * 128;

    // ---- stage all four 128x64 bf16 tiles via cp.async (swizzled) ----
    const uint4* Uh4 = (const uint4*)g_Uh;
    const uint4* Ul4 = (const uint4*)g_Ul;
    const uint4* Vh4 = (const uint4*)g_Vh;
    const uint4* Vl4 = (const uint4*)g_Vl;
#pragma unroll
    for (int c = 0; c < 4; c++) {
        int i = tid + c * 256;
        int row = i >> 3, ch = i & 7;
        uint32_t sw = SWZ128(row * 128 + ch * 16);
        cpa16(sb + SM_AH + sw, &Uh4[(bM + row) * 8 + ch]);
        cpa16(sb + SM_AL + sw, &Ul4[(bM + row) * 8 + ch]);
        cpa16(sb + SM_BH + sw, &Vh4[(bN + row) * 8 + ch]);
        cpa16(sb + SM_BL + sw, &Vl4[(bN + row) * 8 + ch]);
    }
    CP_COMMIT();
    CP_WAIT0();
    __syncthreads();

    const int mw = (wid & 1) * 64;       // warp m offset
    const int nw = (wid >> 1) * 32;      // warp n offset
    const int t8 = lid >> 3, r8 = lid & 7;

    float acc[4][4][4];
#pragma unroll
    for (int mi = 0; mi < 4; mi++)
#pragma unroll
        for (int ni = 0; ni < 4; ni++)
#pragma unroll
            for (int j = 0; j < 4; j++) acc[mi][ni][j] = 0.f;

    const uint32_t aOffs[3] = {SM_AH, SM_AH, SM_AL};
    const uint32_t bOffs[3] = {SM_BH, SM_BL, SM_BH};

#pragma unroll
    for (int p = 0; p < 3; p++) {
        const uint32_t aBase = sb + aOffs[p];
        const uint32_t bBase = sb + bOffs[p];
#pragma unroll
        for (int s = 0; s < 4; s++) {    // k-steps of 16
            uint32_t af[4][4], bf[4][2];
#pragma unroll
            for (int mi = 0; mi < 4; mi++) {
                int row = mw + mi * 16 + r8 + (t8 & 1) * 8;
                int ch = 2 * s + (t8 >> 1);
                ldm_x4(af[mi], aBase + SWZ128(row * 128 + ch * 16));
            }
#pragma unroll
            for (int ni = 0; ni < 4; ni++) {
                int row = nw + ni * 8 + r8;
                int ch = 2 * s + (t8 & 1);
                ldm_x2(bf[ni], bBase + SWZ128(row * 128 + ch * 16));
            }
#pragma unroll
            for (int mi = 0; mi < 4; mi++)
#pragma unroll
                for (int ni = 0; ni < 4; ni++)
                    mma16816(acc[mi][ni], af[mi], bf[ni]);
        }
    }

    // ---- epilogue: direct float2 stores ----
    const int qr = lid >> 2;
    const int qc = (lid & 3) * 2;
#pragma unroll
    for (int mi = 0; mi < 4; mi++) {
        long row0 = bM + mw + mi * 16 + qr;
#pragma unroll
        for (int ni = 0; ni < 4; ni++) {
            long col = bN + nw + ni * 8 + qc;
            *(float2*)&C[row0 * NB + col] =
                make_float2(acc[mi][ni][0], acc[mi][ni][1]);
            *(float2*)&C[(row0 + 8) * NB + col] =
                make_float2(acc[mi][ni][2], acc[mi][ni][3]);
        }
    }
}

// ---------------------------------------------------------------------------
extern "C" void kernel_launch(void* const* d_in, const int* in_sizes, int n_in,
                              void* d_out, int out_size)
{
    const int*   user_ids         = (const int*)  d_in[0];
    const int*   item_ids         = (const int*)  d_in[1];
    const int*   social_neighbors = (const int*)  d_in[2];
    const float* attention_mask   = (const float*)d_in[3];
    const float* user_table       = (const float*)d_in[4];
    const float* item_table       = (const float*)d_in[5];
    const float* Ws               = (const float*)d_in[6];
    const float* bs               = (const float*)d_in[7];
    float* out = (float*)d_out;

    cudaFuncSetAttribute(score_gemm_mma,
                         cudaFuncAttributeMaxDynamicSharedMemorySize, SM_GEMM);

    gather_mlp<<<NB / 8, 256>>>(user_ids, item_ids, social_neighbors,
                                attention_mask, user_table, item_table,
                                Ws, bs);

    dim3 grid(NB / 128, NB / 128);
    score_gemm_mma<<<grid, 256, SM_GEMM>>>(out);
}

// round 7
// speedup vs baseline: 1.7259x; 1.7259x over previous
#include <cuda_runtime.h>
#include <cuda_bf16.h>
#include <cstdint>

#define NB   4096
#define NK   50
#define ND   64
#define NL   3

// ---------------- scratch (device globals; no allocation allowed) -----------
__device__ __nv_bfloat16 g_Uh[NB * ND];
__device__ __nv_bfloat16 g_Ul[NB * ND];
__device__ __nv_bfloat16 g_Vh[NB * ND];
__device__ __nv_bfloat16 g_Vl[NB * ND];

#define SWZ128(o) ((uint32_t)(o) ^ (((uint32_t)(o) >> 3) & 0x70u))

__device__ __forceinline__ uint32_t smem_u32(const void* p) {
    uint32_t a;
    asm("{ .reg .u64 t; cvta.to.shared.u64 t, %1; cvt.u32.u64 %0, t; }"
        : "=r"(a) : "l"(p));
    return a;
}

__device__ __forceinline__ void ldm_x4(uint32_t* r, uint32_t addr) {
    asm volatile("ldmatrix.sync.aligned.m8n8.x4.shared.b16 {%0,%1,%2,%3}, [%4];"
                 : "=r"(r[0]), "=r"(r[1]), "=r"(r[2]), "=r"(r[3]) : "r"(addr));
}
__device__ __forceinline__ void ldm_x2(uint32_t* r, uint32_t addr) {
    asm volatile("ldmatrix.sync.aligned.m8n8.x2.shared.b16 {%0,%1}, [%2];"
                 : "=r"(r[0]), "=r"(r[1]) : "r"(addr));
}
__device__ __forceinline__ void mma16816(float* d, const uint32_t* a,
                                         const uint32_t* b) {
    asm volatile(
        "mma.sync.aligned.m16n8k16.row.col.f32.bf16.bf16.f32 "
        "{%0,%1,%2,%3}, {%4,%5,%6,%7}, {%8,%9}, {%0,%1,%2,%3};"
        : "+f"(d[0]), "+f"(d[1]), "+f"(d[2]), "+f"(d[3])
        : "r"(a[0]), "r"(a[1]), "r"(a[2]), "r"(a[3]), "r"(b[0]), "r"(b[1]));
}

// ---------------------------------------------------------------------------
// Kernel A: gather + weighted neighbor sums (w, w^2, w^3) + 3-layer MLP
//           emits bf16 hi/lo split of U and V. Dynamic smem (63.8 KB).
// Block: 256 threads = 16 rows x 16 lanes (float4 each).  [R4 proven version]
// ---------------------------------------------------------------------------
#define GA_SMEM ((NL * ND * 68 + NL * ND + 16 * 64 + 16 * 64 + 16 * 64) * 4)

__global__ __launch_bounds__(256)
void gather_mlp(const int* __restrict__ user_ids,
                const int* __restrict__ item_ids,
                const int* __restrict__ nbr,
                const float* __restrict__ mask,
                const float* __restrict__ ut,
                const float* __restrict__ itab,
                const float* __restrict__ Ws,
                const float* __restrict__ bsv)
{
    extern __shared__ float dsm[];
    float* s_W = dsm;                        // [l][in][68] transposed, padded
    float* s_b = s_W + NL * ND * 68;         // [l][64]
    float* s_x = s_b + NL * ND;              // [16][64]
    float* s_m = s_x + 16 * 64;              // [16][64] (NK=50 used)
    int*   s_n = (int*)(s_m + 16 * 64);      // [16][64]

    const int tid = threadIdx.x;
    const int r = tid >> 4;          // 0..15
    const int q = tid & 15;          // 0..15 (float4 lane)
    const int b0 = blockIdx.x * 16;
    const int b = b0 + r;

    for (int i = tid; i < 16 * NK; i += 256) {
        int rr = i / NK, kk = i - rr * NK;
        int g = (b0 + rr) * NK + kk;
        s_n[rr * 64 + kk] = nbr[g];
        s_m[rr * 64 + kk] = mask[g];
    }
    // stage W transposed: s_W[l][in][out] = Ws[l][out][in]
    for (int i = tid; i < NL * ND * ND; i += 256) {
        int l = i >> 12, rem = i & 4095;
        int o = rem >> 6, in_ = rem & 63;
        s_W[(l * ND + in_) * 68 + o] = Ws[i];
    }
    for (int i = tid; i < NL * ND; i += 256)
        s_b[i] = bsv[i];
    __syncthreads();

    // item gather -> bf16 split
    {
        float4 v = *(const float4*)&itab[(long)item_ids[b] * ND + q * 4];
        float f[4] = {v.x, v.y, v.z, v.w};
        __nv_bfloat16 h0 = __float2bfloat16(f[0]), h1 = __float2bfloat16(f[1]);
        __nv_bfloat16 h2 = __float2bfloat16(f[2]), h3 = __float2bfloat16(f[3]);
        __nv_bfloat162 h01(h0, h1), h23(h2, h3);
        __nv_bfloat162 l01(__float2bfloat16(f[0] - __bfloat162float(h0)),
                           __float2bfloat16(f[1] - __bfloat162float(h1)));
        __nv_bfloat162 l23(__float2bfloat16(f[2] - __bfloat162float(h2)),
                           __float2bfloat16(f[3] - __bfloat162float(h3)));
        int off = b * ND + q * 4;
        *(__nv_bfloat162*)&g_Vh[off] = h01; *(__nv_bfloat162*)&g_Vh[off + 2] = h23;
        *(__nv_bfloat162*)&g_Vl[off] = l01; *(__nv_bfloat162*)&g_Vl[off + 2] = l23;
    }

    float4 u = *(const float4*)&ut[(long)user_ids[b] * ND + q * 4];

    // one pass over neighbors: weighted sums for w, w^2, w^3
    float a1x=0,a1y=0,a1z=0,a1w=0, a2x=0,a2y=0,a2z=0,a2w=0, a3x=0,a3y=0,a3z=0,a3w=0;
#pragma unroll
    for (int kb = 0; kb < NK; kb += 10) {
        float4 vv[10]; float ww[10];
#pragma unroll
        for (int j = 0; j < 10; j++) {
            int n = s_n[r * 64 + kb + j];
            ww[j] = s_m[r * 64 + kb + j];
            vv[j] = *(const float4*)&ut[(long)n * ND + q * 4];
        }
#pragma unroll
        for (int j = 0; j < 10; j++) {
            float w = ww[j];
            float tx = w * vv[j].x, ty = w * vv[j].y, tz = w * vv[j].z, tw = w * vv[j].w;
            a1x += tx; a1y += ty; a1z += tz; a1w += tw;
            tx *= w; ty *= w; tz *= w; tw *= w;
            a2x += tx; a2y += ty; a2z += tz; a2w += tw;
            tx *= w; ty *= w; tz *= w; tw *= w;
            a3x += tx; a3y += ty; a3z += tz; a3w += tw;
        }
    }
    const float inv = 1.0f / (float)NK;
    float4 sums[3];
    sums[0] = make_float4(a1x*inv, a1y*inv, a1z*inv, a1w*inv);
    sums[1] = make_float4(a2x*inv, a2y*inv, a2z*inv, a2w*inv);
    sums[2] = make_float4(a3x*inv, a3y*inv, a3z*inv, a3w*inv);

    float4 x = u;
#pragma unroll
    for (int l = 0; l < NL; l++) {
        float4 xin = make_float4(x.x + sums[l].x, x.y + sums[l].y,
                                 x.z + sums[l].z, x.w + sums[l].w);
        *(float4*)&s_x[r * 64 + q * 4] = xin;
        __syncthreads();
        float4 acc = *(const float4*)&s_b[l * 64 + q * 4];
#pragma unroll
        for (int i = 0; i < ND; i++) {
            float xi = s_x[r * 64 + i];
            float4 w4 = *(const float4*)&s_W[(l * ND + i) * 68 + q * 4];
            acc.x = fmaf(xi, w4.x, acc.x);
            acc.y = fmaf(xi, w4.y, acc.y);
            acc.z = fmaf(xi, w4.z, acc.z);
            acc.w = fmaf(xi, w4.w, acc.w);
        }
        x = make_float4(fmaxf(acc.x, 0.f), fmaxf(acc.y, 0.f),
                        fmaxf(acc.z, 0.f), fmaxf(acc.w, 0.f));
        __syncthreads();
    }

    // U bf16 split
    {
        float f[4] = {x.x, x.y, x.z, x.w};
        __nv_bfloat16 h0 = __float2bfloat16(f[0]), h1 = __float2bfloat16(f[1]);
        __nv_bfloat16 h2 = __float2bfloat16(f[2]), h3 = __float2bfloat16(f[3]);
        __nv_bfloat162 h01(h0, h1), h23(h2, h3);
        __nv_bfloat162 l01(__float2bfloat16(f[0] - __bfloat162float(h0)),
                           __float2bfloat16(f[1] - __bfloat162float(h1)));
        __nv_bfloat162 l23(__float2bfloat16(f[2] - __bfloat162float(h2)),
                           __float2bfloat16(f[3] - __bfloat162float(h3)));
        int off = b * ND + q * 4;
        *(__nv_bfloat162*)&g_Uh[off] = h01; *(__nv_bfloat162*)&g_Uh[off + 2] = h23;
        *(__nv_bfloat162*)&g_Ul[off] = l01; *(__nv_bfloat162*)&g_Ul[off + 2] = l23;
    }
}

// ---------------------------------------------------------------------------
// Kernel B: C = U @ V^T via mma.sync m16n8k16 bf16, hi/lo split (3 products).
// CTA 128x128, 8 warps (2m x 4n), warp tile 64x32. K=64 smem-resident.
// K-MAJOR mainloop: per k-step load Ah/Al/Bh/Bl frags ONCE, then 48 MMAs.
// No min-blocks bound (regs ~140, 1 CTA/SM) -> no spills.
// ---------------------------------------------------------------------------
#define SM_AH 0
#define SM_AL 16384
#define SM_BH 32768
#define SM_BL 49152
#define SM_GEMM 65536

__global__ __launch_bounds__(256)
void score_gemm_mma(float* __restrict__ C)
{
    extern __shared__ char smem[];
    const uint32_t sb = smem_u32(smem);
    const int tid = threadIdx.x;
    const int wid = tid >> 5, lid = tid & 31;
    const int bM = blockIdx.y * 128;
    const int bN = blockIdx.x * 128;

    // ---- stage all four 128x64 bf16 tiles (swizzled 16B chunks) ----
    const uint4* Uh4 = (const uint4*)g_Uh;
    const uint4* Ul4 = (const uint4*)g_Ul;
    const uint4* Vh4 = (const uint4*)g_Vh;
    const uint4* Vl4 = (const uint4*)g_Vl;
#pragma unroll
    for (int c = 0; c < 4; c++) {
        int i = tid + c * 256;
        int row = i >> 3, ch = i & 7;
        uint32_t sw = SWZ128(row * 128 + ch * 16);
        *(uint4*)(smem + SM_AH + sw) = Uh4[(bM + row) * 8 + ch];
        *(uint4*)(smem + SM_AL + sw) = Ul4[(bM + row) * 8 + ch];
        *(uint4*)(smem + SM_BH + sw) = Vh4[(bN + row) * 8 + ch];
        *(uint4*)(smem + SM_BL + sw) = Vl4[(bN + row) * 8 + ch];
    }
    __syncthreads();

    const int mw = (wid & 1) * 64;       // warp m offset
    const int nw = (wid >> 1) * 32;      // warp n offset
    const int t8 = lid >> 3, r8 = lid & 7;

    float acc[4][4][4];
#pragma unroll
    for (int mi = 0; mi < 4; mi++)
#pragma unroll
        for (int ni = 0; ni < 4; ni++)
#pragma unroll
            for (int j = 0; j < 4; j++) acc[mi][ni][j] = 0.f;

#pragma unroll
    for (int s = 0; s < 4; s++) {        // k-steps of 16
        uint32_t ah[4][4], al[4][4], bh[4][2], bl[4][2];
        {
            int arow = r8 + (t8 & 1) * 8;
            int ach  = 2 * s + (t8 >> 1);
#pragma unroll
            for (int mi = 0; mi < 4; mi++) {
                uint32_t sw = SWZ128((mw + mi * 16 + arow) * 128 + ach * 16);
                ldm_x4(ah[mi], sb + SM_AH + sw);
                ldm_x4(al[mi], sb + SM_AL + sw);
            }
            int bch = 2 * s + (t8 & 1);
#pragma unroll
            for (int ni = 0; ni < 4; ni++) {
                uint32_t sw = SWZ128((nw + ni * 8 + r8) * 128 + bch * 16);
                ldm_x2(bh[ni], sb + SM_BH + sw);
                ldm_x2(bl[ni], sb + SM_BL + sw);
            }
        }
        // 48 back-to-back MMAs, frags each read once
#pragma unroll
        for (int mi = 0; mi < 4; mi++)
#pragma unroll
            for (int ni = 0; ni < 4; ni++) {
                mma16816(acc[mi][ni], ah[mi], bh[ni]);
                mma16816(acc[mi][ni], ah[mi], bl[ni]);
                mma16816(acc[mi][ni], al[mi], bh[ni]);
            }
    }

    // ---- epilogue: direct float2 stores (32B sectors, L2-resident C) ----
    const int qr = lid >> 2;
    const int qc = (lid & 3) * 2;
#pragma unroll
    for (int mi = 0; mi < 4; mi++) {
        long row0 = bM + mw + mi * 16 + qr;
#pragma unroll
        for (int ni = 0; ni < 4; ni++) {
            long col = bN + nw + ni * 8 + qc;
            *(float2*)&C[row0 * NB + col] =
                make_float2(acc[mi][ni][0], acc[mi][ni][1]);
            *(float2*)&C[(row0 + 8) * NB + col] =
                make_float2(acc[mi][ni][2], acc[mi][ni][3]);
        }
    }
}

// ---------------------------------------------------------------------------
extern "C" void kernel_launch(void* const* d_in, const int* in_sizes, int n_in,
                              void* d_out, int out_size)
{
    const int*   user_ids         = (const int*)  d_in[0];
    const int*   item_ids         = (const int*)  d_in[1];
    const int*   social_neighbors = (const int*)  d_in[2];
    const float* attention_mask   = (const float*)d_in[3];
    const float* user_table       = (const float*)d_in[4];
    const float* item_table       = (const float*)d_in[5];
    const float* Ws               = (const float*)d_in[6];
    const float* bs               = (const float*)d_in[7];
    float* out = (float*)d_out;

    cudaFuncSetAttribute(gather_mlp,
                         cudaFuncAttributeMaxDynamicSharedMemorySize, GA_SMEM);
    cudaFuncSetAttribute(score_gemm_mma,
                         cudaFuncAttributeMaxDynamicSharedMemorySize, SM_GEMM);

    gather_mlp<<<NB / 16, 256, GA_SMEM>>>(user_ids, item_ids, social_neighbors,
                                          attention_mask, user_table,
                                          item_table, Ws, bs);

    dim3 grid(NB / 128, NB / 128);
    score_gemm_mma<<<grid, 256, SM_GEMM>>>(out);
}

// round 9
// speedup vs baseline: 2.0421x; 1.1832x over previous
#include <cuda_runtime.h>
#include <cuda_bf16.h>
#include <cstdint>

#define NB   4096
#define NK   50
#define ND   64
#define NL   3
#define NTILES 1024        // 32x32 tiles of 128x128

// ---------------- scratch (device globals; no allocation allowed) -----------
__device__ __nv_bfloat16 g_Uh[NB * ND];
__device__ __nv_bfloat16 g_Ul[NB * ND];
__device__ __nv_bfloat16 g_Vh[NB * ND];
__device__ __nv_bfloat16 g_Vl[NB * ND];

#define SWZ128(o) ((uint32_t)(o) ^ (((uint32_t)(o) >> 3) & 0x70u))

__device__ __forceinline__ uint32_t smem_u32(const void* p) {
    uint32_t a;
    asm("{ .reg .u64 t; cvta.to.shared.u64 t, %1; cvt.u32.u64 %0, t; }"
        : "=r"(a) : "l"(p));
    return a;
}
__device__ __forceinline__ void cpa16(uint32_t dst, const void* src) {
    asm volatile("cp.async.cg.shared.global [%0], [%1], 16;"
                 :: "r"(dst), "l"(src) : "memory");
}
#define CP_COMMIT() asm volatile("cp.async.commit_group;" ::: "memory")
#define CP_WAIT(n)  asm volatile("cp.async.wait_group %0;" :: "n"(n) : "memory")

__device__ __forceinline__ void ldm_x4(uint32_t* r, uint32_t addr) {
    asm volatile("ldmatrix.sync.aligned.m8n8.x4.shared.b16 {%0,%1,%2,%3}, [%4];"
                 : "=r"(r[0]), "=r"(r[1]), "=r"(r[2]), "=r"(r[3]) : "r"(addr));
}
__device__ __forceinline__ void ldm_x2(uint32_t* r, uint32_t addr) {
    asm volatile("ldmatrix.sync.aligned.m8n8.x2.shared.b16 {%0,%1}, [%2];"
                 : "=r"(r[0]), "=r"(r[1]) : "r"(addr));
}
__device__ __forceinline__ void mma16816(float* d, const uint32_t* a,
                                         const uint32_t* b) {
    asm volatile(
        "mma.sync.aligned.m16n8k16.row.col.f32.bf16.bf16.f32 "
        "{%0,%1,%2,%3}, {%4,%5,%6,%7}, {%8,%9}, {%0,%1,%2,%3};"
        : "+f"(d[0]), "+f"(d[1]), "+f"(d[2]), "+f"(d[3])
        : "r"(a[0]), "r"(a[1]), "r"(a[2]), "r"(a[3]), "r"(b[0]), "r"(b[1]));
}

// ---------------------------------------------------------------------------
// Kernel A: gather + weighted neighbor sums (w, w^2, w^3) + 3-layer MLP.
// 512 threads = 16 rows x 32 lanes (float2 per lane). Grid 256.
// W staged ONCE, transposed, pitch 68. Dynamic smem 63.8 KB.
// ---------------------------------------------------------------------------
#define GA_SMEM ((NL * ND * 68 + NL * ND + 16 * 64 + 16 * 64 + 16 * 64) * 4)

__global__ __launch_bounds__(512)
void gather_mlp(const int* __restrict__ user_ids,
                const int* __restrict__ item_ids,
                const int* __restrict__ nbr,
                const float* __restrict__ mask,
                const float* __restrict__ ut,
                const float* __restrict__ itab,
                const float* __restrict__ Ws,
                const float* __restrict__ bsv)
{
    extern __shared__ float dsm[];
    float* s_W = dsm;                        // [l][in][68] transposed, padded
    float* s_b = s_W + NL * ND * 68;         // [l][64]
    float* s_x = s_b + NL * ND;              // [16][64]
    float* s_m = s_x + 16 * 64;              // [16][64] (NK=50 used)
    int*   s_n = (int*)(s_m + 16 * 64);      // [16][64]

    const int tid = threadIdx.x;
    const int r = tid >> 5;          // 0..15 row
    const int q = tid & 31;          // 0..31 lane -> dims {2q, 2q+1}
    const int b0 = blockIdx.x * 16;
    const int b = b0 + r;

    for (int i = tid; i < 16 * NK; i += 512) {
        int rr = i / NK, kk = i - rr * NK;
        int g = (b0 + rr) * NK + kk;
        s_n[rr * 64 + kk] = nbr[g];
        s_m[rr * 64 + kk] = mask[g];
    }
    // stage W transposed: s_W[l][in][out] = Ws[l][out][in]
    for (int i = tid; i < NL * ND * ND; i += 512) {
        int l = i >> 12, rem = i & 4095;
        int o = rem >> 6, in_ = rem & 63;
        s_W[(l * ND + in_) * 68 + o] = Ws[i];
    }
    for (int i = tid; i < NL * ND; i += 512)
        s_b[i] = bsv[i];
    __syncthreads();

    // item gather -> bf16 split
    {
        float2 v = *(const float2*)&itab[(long)item_ids[b] * ND + 2 * q];
        __nv_bfloat16 h0 = __float2bfloat16(v.x), h1 = __float2bfloat16(v.y);
        __nv_bfloat162 hh(h0, h1);
        __nv_bfloat162 ll(__float2bfloat16(v.x - __bfloat162float(h0)),
                          __float2bfloat16(v.y - __bfloat162float(h1)));
        int off = b * ND + 2 * q;
        *(__nv_bfloat162*)&g_Vh[off] = hh;
        *(__nv_bfloat162*)&g_Vl[off] = ll;
    }

    float2 u = *(const float2*)&ut[(long)user_ids[b] * ND + 2 * q];

    // one pass over neighbors: weighted sums for w, w^2, w^3
    float a1x=0,a1y=0, a2x=0,a2y=0, a3x=0,a3y=0;
#pragma unroll
    for (int kb = 0; kb < NK; kb += 10) {
        float2 vv[10]; float ww[10];
#pragma unroll
        for (int j = 0; j < 10; j++) {
            int n = s_n[r * 64 + kb + j];
            ww[j] = s_m[r * 64 + kb + j];
            vv[j] = *(const float2*)&ut[(long)n * ND + 2 * q];
        }
#pragma unroll
        for (int j = 0; j < 10; j++) {
            float w = ww[j];
            float tx = w * vv[j].x, ty = w * vv[j].y;
            a1x += tx; a1y += ty;
            tx *= w; ty *= w;
            a2x += tx; a2y += ty;
            tx *= w; ty *= w;
            a3x += tx; a3y += ty;
        }
    }
    const float inv = 1.0f / (float)NK;
    float2 sums[3] = { make_float2(a1x*inv, a1y*inv),
                       make_float2(a2x*inv, a2y*inv),
                       make_float2(a3x*inv, a3y*inv) };

    float2 x = u;
#pragma unroll
    for (int l = 0; l < NL; l++) {
        s_x[r * 64 + 2*q]     = x.x + sums[l].x;
        s_x[r * 64 + 2*q + 1] = x.y + sums[l].y;
        __syncthreads();
        float ax = s_b[l * 64 + 2*q], ay = s_b[l * 64 + 2*q + 1];
#pragma unroll
        for (int i = 0; i < ND; i++) {
            float xi = s_x[r * 64 + i];                       // broadcast
            float2 w2 = *(const float2*)&s_W[(l * ND + i) * 68 + 2*q];
            ax = fmaf(xi, w2.x, ax);
            ay = fmaf(xi, w2.y, ay);
        }
        x = make_float2(fmaxf(ax, 0.f), fmaxf(ay, 0.f));
        __syncthreads();
    }

    // U bf16 split
    {
        __nv_bfloat16 h0 = __float2bfloat16(x.x), h1 = __float2bfloat16(x.y);
        __nv_bfloat162 hh(h0, h1);
        __nv_bfloat162 ll(__float2bfloat16(x.x - __bfloat162float(h0)),
                          __float2bfloat16(x.y - __bfloat162float(h1)));
        int off = b * ND + 2 * q;
        *(__nv_bfloat162*)&g_Uh[off] = hh;
        *(__nv_bfloat162*)&g_Ul[off] = ll;
    }
}

// ---------------------------------------------------------------------------
// Kernel B: persistent C = U @ V^T, mma.sync bf16 hi/lo split (3 products).
// Grid 148 (1 CTA/SM). Each CTA loops tiles with 2-stage cp.async pipeline:
// prefetch next 128x128 tile set (64 KB) into the idle buffer while
// computing the current one. smem = 2 x 64 KB.
// ---------------------------------------------------------------------------
#define SM_AH 0
#define SM_AL 16384
#define SM_BH 32768
#define SM_BL 49152
#define BUFSZ 65536
#define SM_GEMM (2 * BUFSZ)
#define GGRID 148

__device__ __forceinline__ void stage_tile(uint32_t sbuf, int tile, int tid) {
    const int bM = (tile >> 5) * 128;
    const int bN = (tile & 31) * 128;
    const uint4* Uh4 = (const uint4*)g_Uh;
    const uint4* Ul4 = (const uint4*)g_Ul;
    const uint4* Vh4 = (const uint4*)g_Vh;
    const uint4* Vl4 = (const uint4*)g_Vl;
#pragma unroll
    for (int c = 0; c < 4; c++) {
        int i = tid + c * 256;
        int row = i >> 3, ch = i & 7;
        uint32_t sw = SWZ128(row * 128 + ch * 16);
        cpa16(sbuf + SM_AH + sw, &Uh4[(bM + row) * 8 + ch]);
        cpa16(sbuf + SM_AL + sw, &Ul4[(bM + row) * 8 + ch]);
        cpa16(sbuf + SM_BH + sw, &Vh4[(bN + row) * 8 + ch]);
        cpa16(sbuf + SM_BL + sw, &Vl4[(bN + row) * 8 + ch]);
    }
}

__global__ __launch_bounds__(256)
void score_gemm_mma(float* __restrict__ C)
{
    extern __shared__ char smem[];
    const uint32_t sb = smem_u32(smem);
    const int tid = threadIdx.x;
    const int wid = tid >> 5, lid = tid & 31;

    const int mw = (wid & 1) * 64;       // warp m offset
    const int nw = (wid >> 1) * 32;      // warp n offset
    const int t8 = lid >> 3, r8 = lid & 7;
    const int qr = lid >> 2, qc = (lid & 3) * 2;

    int t = blockIdx.x;
    if (t >= NTILES) return;
    stage_tile(sb, t, tid);
    CP_COMMIT();

    int buf = 0;
    for (; t < NTILES; t += GGRID) {
        const int tn = t + GGRID;
        if (tn < NTILES) {
            stage_tile(sb + (buf ^ 1) * BUFSZ, tn, tid);
            CP_COMMIT();
            CP_WAIT(1);                 // current buffer complete
        } else {
            CP_WAIT(0);
        }
        __syncthreads();

        const uint32_t base = sb + buf * BUFSZ;
        float acc[4][4][4];
#pragma unroll
        for (int mi = 0; mi < 4; mi++)
#pragma unroll
            for (int ni = 0; ni < 4; ni++)
#pragma unroll
                for (int j = 0; j < 4; j++) acc[mi][ni][j] = 0.f;

#pragma unroll
        for (int s = 0; s < 4; s++) {    // k-steps of 16
            uint32_t ah[4][4], al[4][4], bh[4][2], bl[4][2];
            {
                int arow = r8 + (t8 & 1) * 8;
                int ach  = 2 * s + (t8 >> 1);
#pragma unroll
                for (int mi = 0; mi < 4; mi++) {
                    uint32_t sw = SWZ128((mw + mi * 16 + arow) * 128 + ach * 16);
                    ldm_x4(ah[mi], base + SM_AH + sw);
                    ldm_x4(al[mi], base + SM_AL + sw);
                }
                int bch = 2 * s + (t8 & 1);
#pragma unroll
                for (int ni = 0; ni < 4; ni++) {
                    uint32_t sw = SWZ128((nw + ni * 8 + r8) * 128 + bch * 16);
                    ldm_x2(bh[ni], base + SM_BH + sw);
                    ldm_x2(bl[ni], base + SM_BL + sw);
                }
            }
#pragma unroll
            for (int mi = 0; mi < 4; mi++)
#pragma unroll
                for (int ni = 0; ni < 4; ni++) {
                    mma16816(acc[mi][ni], ah[mi], bh[ni]);
                    mma16816(acc[mi][ni], ah[mi], bl[ni]);
                    mma16816(acc[mi][ni], al[mi], bh[ni]);
                }
        }

        // epilogue
        const long bM = (long)(t >> 5) * 128;
        const long bN = (long)(t & 31) * 128;
#pragma unroll
        for (int mi = 0; mi < 4; mi++) {
            long row0 = bM + mw + mi * 16 + qr;
#pragma unroll
            for (int ni = 0; ni < 4; ni++) {
                long col = bN + nw + ni * 8 + qc;
                *(float2*)&C[row0 * NB + col] =
                    make_float2(acc[mi][ni][0], acc[mi][ni][1]);
                *(float2*)&C[(row0 + 8) * NB + col] =
                    make_float2(acc[mi][ni][2], acc[mi][ni][3]);
            }
        }
        __syncthreads();                 // all reads of buf done before refill
        buf ^= 1;
    }
}

// ---------------------------------------------------------------------------
extern "C" void kernel_launch(void* const* d_in, const int* in_sizes, int n_in,
                              void* d_out, int out_size)
{
    const int*   user_ids         = (const int*)  d_in[0];
    const int*   item_ids         = (const int*)  d_in[1];
    const int*   social_neighbors = (const int*)  d_in[2];
    const float* attention_mask   = (const float*)d_in[3];
    const float* user_table       = (const float*)d_in[4];
    const float* item_table       = (const float*)d_in[5];
    const float* Ws               = (const float*)d_in[6];
    const float* bs               = (const float*)d_in[7];
    float* out = (float*)d_out;

    cudaFuncSetAttribute(gather_mlp,
                         cudaFuncAttributeMaxDynamicSharedMemorySize, GA_SMEM);
    cudaFuncSetAttribute(score_gemm_mma,
                         cudaFuncAttributeMaxDynamicSharedMemorySize, SM_GEMM);

    gather_mlp<<<NB / 16, 512, GA_SMEM>>>(user_ids, item_ids, social_neighbors,
                                          attention_mask, user_table,
                                          item_table, Ws, bs);

    score_gemm_mma<<<GGRID, 256, SM_GEMM>>>(out);
}